// round 17
// baseline (speedup 1.0000x reference)
#include <cuda_runtime.h>
#include <cstdint>
#include <cfloat>

// Chamfer distance via exact grid NN search — ONE WARP PER QUERY-CELL.
// pred/gt: [4, 8192, 3] fp32, N(0,1). Output: scalar fp32.
//
// R16 lesson: warp-per-query is convergent but wastes ~80% of lanes (spans
// ~6-20 pts). Queries in the SAME cell share their 27-cell neighborhood, so:
// warp = query cell, lane = resident query, candidates staged once in smem
// prescaled as {-2px,-2py,-2pz,p2}. Each candidate: LDS.128 broadcast +
// 3 FMA + FMNMX = 5 instr serving up to 32 queries (d = q2 + (p2 - 2pq),
// q2 added once at the end). Descriptors: once per cell, not per query.
// Tail (best > h^2, ~1-3%): ballot + warp-cooperative expanding cube
// (cell coords are warp-uniform).

#define NPTS   8192
#define BATCH  4
#define NGRIDS 8                     // batch x {pred,gt}
#define GB     32
#define GB3    (GB * GB * GB)        // 32768
#define SROW   (GB3 + 4)             // row stride, %4==0 -> int4 aligned
#define XMIN   (-6.0f)
#define H      0.375f                // 12/32, exactly representable
#define INVH   (GB / 12.0f)
#define RBSAFE 0.37495f              // slightly < H: conservative bound
#define NQ     (2 * BATCH * NPTS)    // 65536
#define QBLK   256                   // 8 warps per block
#define NTASKS (NGRIDS * GB3)        // 262144 cell-tasks
#define QGRID  (NTASKS / (QBLK / 32))// 32768 blocks
#define SCALE  4294967296.0          // 2^32 fixed-point for the sum

__device__ int                g_start[NGRIDS][SROW];
__device__ float4             g_pts[NGRIDS][NPTS];
__device__ unsigned long long g_sum;
__device__ unsigned int       g_done;

__device__ __forceinline__ int bin1(float v) {
    int c = (int)floorf((v - XMIN) * INVH);
    return min(GB - 1, max(0, c));
}

// ---- K1: fused build. One block per grid: smem histogram -> scan -> CSR ----
__global__ __launch_bounds__(1024, 1)
void cd_build(const float* __restrict__ pred, const float* __restrict__ gt) {
    extern __shared__ int cnt[];            // GB3 ints = 128 KB
    __shared__ int warp_part[32];
    const int g   = blockIdx.x;             // 0..7 = (b<<1)|src
    const int tid = threadIdx.x;
    const int lid = tid & 31, wid = tid >> 5;
    const int s_  = g & 1, b = g >> 1;
    const float* src = (s_ ? gt : pred) + (size_t)b * NPTS * 3;

    if (g == 0 && tid == 0) { g_sum = 0ull; g_done = 0u; }

    #pragma unroll
    for (int k = 0; k < 8; k++)
        ((int4*)cnt)[tid + k * 1024] = make_int4(0, 0, 0, 0);
    __syncthreads();

    int cells[NPTS / 1024];
    #pragma unroll
    for (int k = 0; k < NPTS / 1024; k++) {
        int i = tid + k * 1024;
        const float* p = src + (size_t)i * 3;
        int cx = bin1(p[0]), cy = bin1(p[1]), cz = bin1(p[2]);
        cells[k] = (cz * GB + cy) * GB + cx;
        atomicAdd(&cnt[cells[k]], 1);
    }
    __syncthreads();

    int s = 0;
    int4 c4s[8];
    #pragma unroll
    for (int k = 0; k < 8; k++) {
        c4s[k] = ((int4*)cnt)[tid * 8 + k];
        s += c4s[k].x + c4s[k].y + c4s[k].z + c4s[k].w;
    }
    int incl = s;
    #pragma unroll
    for (int off = 1; off < 32; off <<= 1) {
        int v = __shfl_up_sync(0xFFFFFFFFu, incl, off);
        if (lid >= off) incl += v;
    }
    if (lid == 31) warp_part[wid] = incl;
    __syncthreads();
    if (wid == 0) {
        int w = warp_part[lid];
        int wincl = w;
        #pragma unroll
        for (int off = 1; off < 32; off <<= 1) {
            int v = __shfl_up_sync(0xFFFFFFFFu, wincl, off);
            if (lid >= off) wincl += v;
        }
        warp_part[lid] = wincl - w;
    }
    __syncthreads();
    int run = warp_part[wid] + (incl - s);

    int4* gst = (int4*)&g_start[g][tid * 32];
    #pragma unroll
    for (int k = 0; k < 8; k++) {
        int4 c4 = c4s[k];
        int4 o;
        o.x = run;
        o.y = o.x + c4.x;
        o.z = o.y + c4.y;
        o.w = o.z + c4.z;
        run = o.w + c4.w;
        gst[k] = o;
        ((int4*)cnt)[tid * 8 + k] = o;
    }
    if (tid == 1023) g_start[g][GB3] = run;
    __syncthreads();

    #pragma unroll
    for (int k = 0; k < NPTS / 1024; k++) {
        int i = tid + k * 1024;
        const float* p = src + (size_t)i * 3;
        float x = p[0], y = p[1], z = p[2];
        int pos = atomicAdd(&cnt[cells[k]], 1);
        g_pts[g][pos] = make_float4(x, y, z, 0.0f);
    }
}

// ---- K2: one warp per query-cell ----
__global__ __launch_bounds__(QBLK)
void cd_query(float* __restrict__ out) {
    __shared__ float4 cand[QBLK / 32][32];
    __shared__ unsigned long long wsum[QBLK / 32];

    const int wlocal = threadIdx.x >> 5;
    const int lid    = threadIdx.x & 31;
    const int task   = blockIdx.x * (QBLK / 32) + wlocal;   // 0..262143
    const int cell   = task & (GB3 - 1);
    const int qg     = task >> 15;            // query grid 0..7
    const int dg     = qg ^ 1;                // database grid

    unsigned long long mysum = 0ull;

    const int qs = __ldg(&g_start[qg][cell]);
    const int qe = __ldg(&g_start[qg][cell + 1]);

    if (qs < qe) {
        const int cx = cell & (GB - 1);
        const int cy = (cell >> 5) & (GB - 1);
        const int cz = cell >> 10;
        const int* start  = g_start[dg];
        const float4* pts = g_pts[dg];

        // 9 row descriptors, loaded once per cell (lanes 0..8), broadcast
        const int xa = max(cx - 1, 0), xb = min(cx + 1, GB - 1);
        int sv = 0, ev = 0;
        if (lid < 9) {
            int y = cy + (lid % 3) - 1;
            int z = cz + (lid / 3) - 1;
            bool ok = ((unsigned)y < GB) & ((unsigned)z < GB);
            int base = (z * GB + y) * GB;
            sv = ok ? __ldg(&start[base + xa])     : 0;
            ev = ok ? __ldg(&start[base + xb + 1]) : 0;
        }
        int s_[9], e_[9];
        #pragma unroll
        for (int j = 0; j < 9; j++) {
            s_[j] = __shfl_sync(0xFFFFFFFFu, sv, j);
            e_[j] = __shfl_sync(0xFFFFFFFFu, ev, j);
        }

        for (int q0 = qs; q0 < qe; q0 += 32) {
            const bool valid = (q0 + lid) < qe;
            const int  qi    = min(q0 + lid, qe - 1);
            float4 qv = __ldg(&g_pts[qg][qi]);
            const float qx = qv.x, qy = qv.y, qz = qv.z;
            const float q2 = fmaf(qx, qx, fmaf(qy, qy, qz * qz));

            float tmin = FLT_MAX;

            #pragma unroll
            for (int j = 0; j < 9; j++) {
                for (int c = s_[j]; c < e_[j]; c += 32) {
                    const int cnt  = min(32, e_[j] - c);
                    const int cntR = (cnt + 7) & ~7;
                    float4 cd;
                    if (c + lid < e_[j]) {
                        float4 p = __ldg(&pts[c + lid]);
                        float p2 = fmaf(p.x, p.x, fmaf(p.y, p.y, p.z * p.z));
                        cd = make_float4(-2.0f * p.x, -2.0f * p.y, -2.0f * p.z, p2);
                    } else {
                        cd = make_float4(0.0f, 0.0f, 0.0f, FLT_MAX);
                    }
                    cand[wlocal][lid] = cd;
                    __syncwarp();
                    for (int u = 0; u < cntR; u += 8) {
                        #pragma unroll
                        for (int v = 0; v < 8; v++) {
                            float4 cc = cand[wlocal][u + v];
                            float tt = fmaf(cc.x, qx, cc.w);
                            tt = fmaf(cc.y, qy, tt);
                            tmin = fminf(tmin, fmaf(cc.z, qz, tt));
                        }
                    }
                    __syncwarp();
                }
            }

            float best = fmaxf(q2 + tmin, 0.0f);
            if (tmin == FLT_MAX) best = FLT_MAX;   // empty neighborhood

            // tail: warp-cooperative expanding cube for needy lanes (rare)
            unsigned need = __ballot_sync(0xFFFFFFFFu,
                                          valid && best > RBSAFE * RBSAFE);
            while (need) {
                const int src = __ffs(need) - 1;
                need &= need - 1;
                const float tqx = __shfl_sync(0xFFFFFFFFu, qx, src);
                const float tqy = __shfl_sync(0xFFFFFFFFu, qy, src);
                const float tqz = __shfl_sync(0xFFFFFFFFu, qz, src);
                float tb = __shfl_sync(0xFFFFFFFFu, best, src);
                float lm = FLT_MAX;
                int r = 1;
                float rb = RBSAFE;
                while (tb > rb * rb && r < GB) {
                    r++;
                    rb = (float)r * RBSAFE;
                    const int z0i = max(cz - r, 0), z1i = min(cz + r, GB - 1);
                    const int y0i = max(cy - r, 0), y1i = min(cy + r, GB - 1);
                    const int xra = max(cx - r, 0), xrb = min(cx + r, GB - 1);
                    for (int z = z0i; z <= z1i; z++)
                        for (int y = y0i; y <= y1i; y++) {
                            const int rbase = (z * GB + y) * GB;
                            const int ss = __ldg(&start[rbase + xra]);
                            const int ee = __ldg(&start[rbase + xrb + 1]);
                            for (int k = ss + lid; k < ee; k += 32) {
                                float4 p = __ldg(&pts[k]);
                                float dx = tqx - p.x, dy = tqy - p.y, dz = tqz - p.z;
                                lm = fminf(lm, fmaf(dx, dx, fmaf(dy, dy, dz * dz)));
                            }
                        }
                    float v = lm;
                    #pragma unroll
                    for (int off = 16; off > 0; off >>= 1)
                        v = fminf(v, __shfl_xor_sync(0xFFFFFFFFu, v, off));
                    tb = fminf(tb, v);
                }
                if (lid == src) best = tb;
            }

            if (valid)
                mysum += (unsigned long long)((double)best * SCALE + 0.5);
        }
    }

    // ---- reduction: warp sum -> block sum -> one atomic per block ----
    #pragma unroll
    for (int off = 16; off > 0; off >>= 1)
        mysum += __shfl_down_sync(0xFFFFFFFFu, mysum, off);
    if (lid == 0) wsum[wlocal] = mysum;
    __syncthreads();
    if (wlocal == 0) {
        unsigned long long bv = (lid < QBLK / 32) ? wsum[lid] : 0ull;
        #pragma unroll
        for (int off = QBLK / 64; off > 0; off >>= 1)
            bv += __shfl_down_sync(0xFFFFFFFFu, bv, off);
        if (lid == 0) {
            atomicAdd(&g_sum, bv);
            __threadfence();
            unsigned int old = atomicAdd(&g_done, 1u);
            if (old == QGRID - 1) {
                unsigned long long total = atomicAdd(&g_sum, 0ull);
                out[0] = (float)((double)total / (SCALE * (double)(BATCH * NPTS)));
            }
        }
    }
}

extern "C" void kernel_launch(void* const* d_in, const int* in_sizes, int n_in,
                              void* d_out, int out_size) {
    const float* pred = (const float*)d_in[0];
    const float* gt   = (const float*)d_in[1];
    float* out        = (float*)d_out;

    static int configured = 0;
    if (!configured) {
        cudaFuncSetAttribute(cd_build, cudaFuncAttributeMaxDynamicSharedMemorySize,
                             GB3 * (int)sizeof(int));
        configured = 1;
    }

    cd_build<<<NGRIDS, 1024, GB3 * sizeof(int)>>>(pred, gt);
    cd_query<<<QGRID, QBLK>>>(out);
}